// round 9
// baseline (speedup 1.0000x reference)
#include <cuda_runtime.h>
#include <cuda_fp16.h>
#include <math.h>

#define N_NODES   10000
#define N_EDGES   640000
#define E_TOT     (N_EDGES + N_NODES)   // with self loops
#define HID       128
#define N_LAYERS  3
#define N_ACT     4096
#define NEG_SLOPE 0.2f
#define ACT_PER_BLK 32

// ---------------- scratch (device globals, no allocation) ----------------
__device__ __align__(16) float  d_h[N_NODES * HID];     // node features (fp32)
__device__ __align__(16) __half d_z16[N_NODES * HID];   // z = h @ W, fp16 (gather-only)
__device__ __align__(16) float  d_zs[N_NODES];          // z . a_src (fp32)
__device__ __align__(16) float  d_zd[N_NODES];          // z . a_dst (fp32)
__device__ int   d_deg[N_NODES];
__device__ int   d_rowptr[N_NODES + 1];
__device__ int   d_cursor[N_NODES];
__device__ int   d_colsrc[E_TOT];         // CSR by dst: src node per incoming edge

// ---------------- CSR build (edge_index is int32: JAX x64 disabled) ----------------
__device__ __forceinline__ void edge_sd(const int* ei, int i, int& s, int& d) {
    if (i < N_EDGES) { s = ei[i]; d = ei[N_EDGES + i]; }
    else             { s = i - N_EDGES; d = i - N_EDGES; }          // self loops
}

__global__ void zero_deg_kernel() {
    int i = blockIdx.x * blockDim.x + threadIdx.x;
    if (i < N_NODES) d_deg[i] = 0;
}

__global__ void count_deg_kernel(const int* __restrict__ ei) {
    int i = blockIdx.x * blockDim.x + threadIdx.x;
    if (i >= E_TOT) return;
    int s, d; edge_sd(ei, i, s, d);
    atomicAdd(&d_deg[d], 1);
}

__global__ void scan_deg_kernel() {
    __shared__ int part[1024];
    int tid = threadIdx.x;
    const int CH = 10;                       // 1024*10 >= 10000
    int start = tid * CH;
    int s = 0;
    #pragma unroll
    for (int i = 0; i < CH; i++) {
        int idx = start + i;
        if (idx < N_NODES) s += d_deg[idx];
    }
    part[tid] = s;
    __syncthreads();
    for (int off = 1; off < 1024; off <<= 1) {
        int v = (tid >= off) ? part[tid - off] : 0;
        __syncthreads();
        part[tid] += v;
        __syncthreads();
    }
    int run = part[tid] - s;                 // exclusive prefix
    #pragma unroll
    for (int i = 0; i < CH; i++) {
        int idx = start + i;
        if (idx < N_NODES) {
            d_rowptr[idx] = run;
            d_cursor[idx] = run;
            run += d_deg[idx];
        }
    }
    if (tid == 0) d_rowptr[N_NODES] = E_TOT;
}

__global__ void scatter_edges_kernel(const int* __restrict__ ei) {
    int i = blockIdx.x * blockDim.x + threadIdx.x;
    if (i >= E_TOT) return;
    int s, d; edge_sd(ei, i, s, d);
    int pos = atomicAdd(&d_cursor[d], 1);
    d_colsrc[pos] = s;
}

// ---------------- GEMM: z = h @ W (fp16 out) + fused zs/zd dots ----------------
// BM=64, BN=128(full), BK=16, 256 threads (8 warps/CTA), 4x8 micro-tile. grid=157.
__global__ __launch_bounds__(256) void gemm_zw_kernel(const float* __restrict__ xin,
                                                      const float* __restrict__ W,
                                                      const float* __restrict__ asrc,
                                                      const float* __restrict__ adst,
                                                      int layer) {
    const float* __restrict__ hsrc = (layer == 0) ? xin : d_h;
    __shared__ float As[16][64];
    __shared__ float Bs[16][128];
    int tid = threadIdx.x;
    int tx = tid & 15, ty = tid >> 4;        // tx: col group (x8), ty: row group (x4), ty 0..15
    int row0 = blockIdx.x * 64;
    float acc[4][8];
    #pragma unroll
    for (int i = 0; i < 4; i++)
        #pragma unroll
        for (int j = 0; j < 8; j++) acc[i][j] = 0.f;

    for (int k0 = 0; k0 < HID; k0 += 16) {
        // A tile: 64 x 16 -> As[k][r]; 256 float4s, 1 per thread
        {
            int v = tid;                  // 0..255
            int r = v >> 2;               // 0..63
            int kk = (v & 3) * 4;         // 0,4,8,12
            float4 val = make_float4(0.f, 0.f, 0.f, 0.f);
            if (row0 + r < N_NODES)
                val = *(const float4*)(hsrc + (size_t)(row0 + r) * HID + k0 + kk);
            As[kk + 0][r] = val.x; As[kk + 1][r] = val.y;
            As[kk + 2][r] = val.z; As[kk + 3][r] = val.w;
        }
        // B tile: 16 x 128 -> Bs[k][c]; 512 float4s, 2 per thread
        #pragma unroll
        for (int i = 0; i < 2; i++) {
            int v = tid * 2 + i;          // 0..511
            int kk = v >> 5;              // 0..15
            int c = (v & 31) * 4;         // 0..124
            *(float4*)&Bs[kk][c] = *(const float4*)(W + (size_t)(k0 + kk) * HID + c);
        }
        __syncthreads();
        #pragma unroll
        for (int k = 0; k < 16; k++) {
            float4 a0 = *(const float4*)&As[k][ty * 4];
            float4 b0 = *(const float4*)&Bs[k][tx * 8];
            float4 b1 = *(const float4*)&Bs[k][tx * 8 + 4];
            float a[4] = {a0.x, a0.y, a0.z, a0.w};
            float b[8] = {b0.x, b0.y, b0.z, b0.w, b1.x, b1.y, b1.z, b1.w};
            #pragma unroll
            for (int i = 0; i < 4; i++)
                #pragma unroll
                for (int j = 0; j < 8; j++) acc[i][j] = fmaf(a[i], b[j], acc[i][j]);
        }
        __syncthreads();
    }

    // fused dots vectors for this thread's 8 columns
    float4 s0 = *(const float4*)(asrc + tx * 8);
    float4 s1 = *(const float4*)(asrc + tx * 8 + 4);
    float4 d0 = *(const float4*)(adst + tx * 8);
    float4 d1 = *(const float4*)(adst + tx * 8 + 4);
    float av[8] = {s0.x, s0.y, s0.z, s0.w, s1.x, s1.y, s1.z, s1.w};
    float dv[8] = {d0.x, d0.y, d0.z, d0.w, d1.x, d1.y, d1.z, d1.w};

    #pragma unroll
    for (int i = 0; i < 4; i++) {
        int r = row0 + ty * 4 + i;
        bool valid = (r < N_NODES);
        if (valid) {
            __half2 h01 = __floats2half2_rn(acc[i][0], acc[i][1]);
            __half2 h23 = __floats2half2_rn(acc[i][2], acc[i][3]);
            __half2 h45 = __floats2half2_rn(acc[i][4], acc[i][5]);
            __half2 h67 = __floats2half2_rn(acc[i][6], acc[i][7]);
            uint4 pk;
            pk.x = *(unsigned*)&h01; pk.y = *(unsigned*)&h23;
            pk.z = *(unsigned*)&h45; pk.w = *(unsigned*)&h67;
            *(uint4*)(d_z16 + (size_t)r * HID + tx * 8) = pk;
        }
        float ps = 0.f, pd = 0.f;
        #pragma unroll
        for (int j = 0; j < 8; j++) {
            ps = fmaf(acc[i][j], av[j], ps);
            pd = fmaf(acc[i][j], dv[j], pd);
        }
        // reduce over the 16 tx-lanes (lane = (ty&1)*16 + tx)
        #pragma unroll
        for (int o = 8; o; o >>= 1) {
            ps += __shfl_xor_sync(0xffffffffu, ps, o);
            pd += __shfl_xor_sync(0xffffffffu, pd, o);
        }
        if (valid && tx == 0) { d_zs[r] = ps; d_zd[r] = pd; }
    }
}

// ---------------- half-warp-split single-pass softmax aggregation ----------------
// 2 edges/iter: lanes 0-15 -> edge j, lanes 16-31 -> edge j+1.
// Each lane loads one uint4 (8 fp16 features); cross-half shfl merges at the end.
__global__ void aggregate_kernel(const float* __restrict__ bvec) {
    int warp = (blockIdx.x * blockDim.x + threadIdx.x) >> 5;
    int lane = threadIdx.x & 31;
    if (warp >= N_NODES) return;
    int half = lane >> 4, hl = lane & 15;
    int beg = d_rowptr[warp], end = d_rowptr[warp + 1];
    float zdn = d_zd[warp];

    float acc[8];
    #pragma unroll
    for (int i = 0; i < 8; i++) acc[i] = 0.f;
    float den = 0.f;

    int j = beg;
    for (; j + 2 <= end; j += 2) {
        int s = d_colsrc[j + half];                  // uniform within half-warp
        float e = d_zs[s] + zdn;
        e = (e > 0.f) ? e : NEG_SLOPE * e;
        float ex = __expf(e);
        uint4 r = ((const uint4*)(d_z16 + (size_t)s * HID))[hl];
        den += ex;
        float2 f0 = __half22float2(*(__half2*)&r.x);
        float2 f1 = __half22float2(*(__half2*)&r.y);
        float2 f2 = __half22float2(*(__half2*)&r.z);
        float2 f3 = __half22float2(*(__half2*)&r.w);
        acc[0] = fmaf(ex, f0.x, acc[0]); acc[1] = fmaf(ex, f0.y, acc[1]);
        acc[2] = fmaf(ex, f1.x, acc[2]); acc[3] = fmaf(ex, f1.y, acc[3]);
        acc[4] = fmaf(ex, f2.x, acc[4]); acc[5] = fmaf(ex, f2.y, acc[5]);
        acc[6] = fmaf(ex, f3.x, acc[6]); acc[7] = fmaf(ex, f3.y, acc[7]);
    }
    if (j < end) {                                   // odd remainder: half 1 contributes 0
        int s = d_colsrc[j];
        float e = d_zs[s] + zdn;
        e = (e > 0.f) ? e : NEG_SLOPE * e;
        float ex = half ? 0.f : __expf(e);
        uint4 r = ((const uint4*)(d_z16 + (size_t)s * HID))[hl];
        den += ex;
        float2 f0 = __half22float2(*(__half2*)&r.x);
        float2 f1 = __half22float2(*(__half2*)&r.y);
        float2 f2 = __half22float2(*(__half2*)&r.z);
        float2 f3 = __half22float2(*(__half2*)&r.w);
        acc[0] = fmaf(ex, f0.x, acc[0]); acc[1] = fmaf(ex, f0.y, acc[1]);
        acc[2] = fmaf(ex, f1.x, acc[2]); acc[3] = fmaf(ex, f1.y, acc[3]);
        acc[4] = fmaf(ex, f2.x, acc[4]); acc[5] = fmaf(ex, f2.y, acc[5]);
        acc[6] = fmaf(ex, f3.x, acc[6]); acc[7] = fmaf(ex, f3.y, acc[7]);
    }

    // merge the two halves
    den += __shfl_xor_sync(0xffffffffu, den, 16);
    #pragma unroll
    for (int i = 0; i < 8; i++) acc[i] += __shfl_xor_sync(0xffffffffu, acc[i], 16);

    if (half == 0) {
        float inv = 1.0f / den;
        float4 b0 = ((const float4*)bvec)[hl * 2];
        float4 b1 = ((const float4*)bvec)[hl * 2 + 1];
        float4 o0, o1;
        o0.x = fmaxf(acc[0] * inv + b0.x, 0.f);
        o0.y = fmaxf(acc[1] * inv + b0.y, 0.f);
        o0.z = fmaxf(acc[2] * inv + b0.z, 0.f);
        o0.w = fmaxf(acc[3] * inv + b0.w, 0.f);
        o1.x = fmaxf(acc[4] * inv + b1.x, 0.f);
        o1.y = fmaxf(acc[5] * inv + b1.y, 0.f);
        o1.z = fmaxf(acc[6] * inv + b1.z, 0.f);
        o1.w = fmaxf(acc[7] * inv + b1.w, 0.f);
        ((float4*)(d_h + (size_t)warp * HID))[hl * 2]     = o0;
        ((float4*)(d_h + (size_t)warp * HID))[hl * 2 + 1] = o1;
    }
}

// ---------------- action MLP: batched, static smem only ----------------
__global__ __launch_bounds__(128) void action_mlp_kernel(
    const int* __restrict__ asrc, const int* __restrict__ adst,
    const int* __restrict__ atype,
    const float* __restrict__ W1, const float* __restrict__ b1,
    const float* __restrict__ W2, const float* __restrict__ b2,
    float* __restrict__ out) {
    __shared__ __align__(16) float feat[ACT_PER_BLK][260];  // 257 used (pad)
    __shared__ float W1t[16][128];
    __shared__ float red[ACT_PER_BLK][4];
    int tid = threadIdx.x;
    int a0 = blockIdx.x * ACT_PER_BLK;

    #pragma unroll
    for (int a = 0; a < ACT_PER_BLK; a++) {
        int s  = asrc[a0 + a];
        int dd = adst[a0 + a];
        feat[a][tid]       = d_h[(size_t)s  * HID + tid];
        feat[a][128 + tid] = d_h[(size_t)dd * HID + tid];
        if (tid == 0) {
            feat[a][256] = (float)atype[a0 + a];
            feat[a][257] = 0.f; feat[a][258] = 0.f; feat[a][259] = 0.f;
        }
    }
    float acc[ACT_PER_BLK];
    float bj = b1[tid];
    #pragma unroll
    for (int a = 0; a < ACT_PER_BLK; a++) acc[a] = bj;
    __syncthreads();

    for (int k0 = 0; k0 < 256; k0 += 16) {
        #pragma unroll
        for (int i = 0; i < 16; i++) W1t[i][tid] = W1[(size_t)(k0 + i) * HID + tid];
        __syncthreads();
        float w[16];
        #pragma unroll
        for (int i = 0; i < 16; i++) w[i] = W1t[i][tid];
        #pragma unroll
        for (int a = 0; a < ACT_PER_BLK; a++) {
            #pragma unroll
            for (int q = 0; q < 4; q++) {
                float4 f = *(const float4*)&feat[a][k0 + q * 4];
                acc[a] = fmaf(f.x, w[q * 4 + 0], acc[a]);
                acc[a] = fmaf(f.y, w[q * 4 + 1], acc[a]);
                acc[a] = fmaf(f.z, w[q * 4 + 2], acc[a]);
                acc[a] = fmaf(f.w, w[q * 4 + 3], acc[a]);
            }
        }
        __syncthreads();
    }
    {
        float w = W1[(size_t)256 * HID + tid];
        #pragma unroll
        for (int a = 0; a < ACT_PER_BLK; a++) acc[a] = fmaf(feat[a][256], w, acc[a]);
    }

    float w2j = W2[tid];
    float b2v = b2[0];
    int lane = tid & 31, wp = tid >> 5;
    #pragma unroll
    for (int a = 0; a < ACT_PER_BLK; a++) {
        float c = fmaxf(acc[a], 0.f) * w2j;
        #pragma unroll
        for (int o = 16; o; o >>= 1) c += __shfl_xor_sync(0xffffffffu, c, o);
        if (lane == 0) red[a][wp] = c;
    }
    __syncthreads();
    if (tid < ACT_PER_BLK)
        out[a0 + tid] = red[tid][0] + red[tid][1] + red[tid][2] + red[tid][3] + b2v;
}

// ---------------- launch ----------------
extern "C" void kernel_launch(void* const* d_in, const int* in_sizes, int n_in,
                              void* d_out, int out_size) {
    const float* x     = (const float*)d_in[0];
    const int*   ei    = (const int*)d_in[1];     // int32 (JAX x64 disabled)
    const int*   a_src = (const int*)d_in[2];     // int32
    const int*   a_dst = (const int*)d_in[3];     // int32
    const int*   a_ty  = (const int*)d_in[4];
    const float* gW    = (const float*)d_in[5];
    const float* ga_s  = (const float*)d_in[6];
    const float* ga_d  = (const float*)d_in[7];
    const float* gb    = (const float*)d_in[8];
    const float* W1    = (const float*)d_in[9];
    const float* b1    = (const float*)d_in[10];
    const float* W2    = (const float*)d_in[11];
    const float* b2    = (const float*)d_in[12];
    float* out = (float*)d_out;

    // CSR build (by dst)
    zero_deg_kernel<<<(N_NODES + 255) / 256, 256>>>();
    count_deg_kernel<<<(E_TOT + 255) / 256, 256>>>(ei);
    scan_deg_kernel<<<1, 1024>>>();
    scatter_edges_kernel<<<(E_TOT + 255) / 256, 256>>>(ei);

    // 3 GAT layers (dots fused into GEMM epilogue; z stored fp16)
    for (int l = 0; l < N_LAYERS; l++) {
        gemm_zw_kernel<<<(N_NODES + 63) / 64, 256>>>(x, gW + (size_t)l * HID * HID,
                                                     ga_s + l * HID, ga_d + l * HID, l);
        aggregate_kernel<<<(N_NODES * 32 + 255) / 256, 256>>>(gb + l * HID);
    }

    // action scoring MLP
    action_mlp_kernel<<<N_ACT / ACT_PER_BLK, 128>>>(a_src, a_dst, a_ty, W1, b1, W2, b2, out);
}

// round 10
// speedup vs baseline: 1.1413x; 1.1413x over previous
#include <cuda_runtime.h>
#include <cuda_fp16.h>
#include <math.h>

#define N_NODES   10000
#define N_EDGES   640000
#define E_TOT     (N_EDGES + N_NODES)   // with self loops
#define HID       128
#define N_LAYERS  3
#define N_ACT     4096
#define NEG_SLOPE 0.2f
#define ACT_PER_BLK 32

// ---------------- scratch (device globals, no allocation) ----------------
__device__ __align__(16) float  d_h[N_NODES * HID];     // node features (fp32)
__device__ __align__(16) __half d_z16[N_NODES * HID];   // z = h @ W, fp16 (gather-only)
__device__ __align__(16) float  d_zs[N_NODES];          // z . a_src (fp32)
__device__ __align__(16) float  d_zd[N_NODES];          // z . a_dst (fp32)
__device__ int   d_deg[N_NODES];
__device__ int   d_rowptr[N_NODES + 1];
__device__ int   d_cursor[N_NODES];
__device__ int   d_colsrc[E_TOT];         // CSR by dst: src node per incoming edge

// ---------------- CSR build (edge_index is int32: JAX x64 disabled) ----------------
__device__ __forceinline__ void edge_sd(const int* ei, int i, int& s, int& d) {
    if (i < N_EDGES) { s = ei[i]; d = ei[N_EDGES + i]; }
    else             { s = i - N_EDGES; d = i - N_EDGES; }          // self loops
}

__global__ void zero_deg_kernel() {
    int i = blockIdx.x * blockDim.x + threadIdx.x;
    if (i < N_NODES) d_deg[i] = 0;
}

__global__ void count_deg_kernel(const int* __restrict__ ei) {
    int i = blockIdx.x * blockDim.x + threadIdx.x;
    if (i >= E_TOT) return;
    int s, d; edge_sd(ei, i, s, d);
    atomicAdd(&d_deg[d], 1);
}

__global__ void scan_deg_kernel() {
    __shared__ int part[1024];
    int tid = threadIdx.x;
    const int CH = 10;                       // 1024*10 >= 10000
    int start = tid * CH;
    int s = 0;
    #pragma unroll
    for (int i = 0; i < CH; i++) {
        int idx = start + i;
        if (idx < N_NODES) s += d_deg[idx];
    }
    part[tid] = s;
    __syncthreads();
    for (int off = 1; off < 1024; off <<= 1) {
        int v = (tid >= off) ? part[tid - off] : 0;
        __syncthreads();
        part[tid] += v;
        __syncthreads();
    }
    int run = part[tid] - s;                 // exclusive prefix
    #pragma unroll
    for (int i = 0; i < CH; i++) {
        int idx = start + i;
        if (idx < N_NODES) {
            d_rowptr[idx] = run;
            d_cursor[idx] = run;
            run += d_deg[idx];
        }
    }
    if (tid == 0) d_rowptr[N_NODES] = E_TOT;
}

__global__ void scatter_edges_kernel(const int* __restrict__ ei) {
    int i = blockIdx.x * blockDim.x + threadIdx.x;
    if (i >= E_TOT) return;
    int s, d; edge_sd(ei, i, s, d);
    int pos = atomicAdd(&d_cursor[d], 1);
    d_colsrc[pos] = s;
}

// ---------------- GEMM: z = h @ W (fp16 out) + fused zs/zd dots ----------------
// BM=128, BN=128(full), BK=16, 256 threads (8 warps/CTA), 8x8 micro-tile. grid=79.
__global__ __launch_bounds__(256) void gemm_zw_kernel(const float* __restrict__ xin,
                                                      const float* __restrict__ W,
                                                      const float* __restrict__ asrc,
                                                      const float* __restrict__ adst,
                                                      int layer) {
    const float* __restrict__ hsrc = (layer == 0) ? xin : d_h;
    __shared__ float As[16][128];
    __shared__ float Bs[16][128];
    int tid = threadIdx.x;
    int tx = tid & 15, ty = tid >> 4;
    int row0 = blockIdx.x * 128;
    float acc[8][8];
    #pragma unroll
    for (int i = 0; i < 8; i++)
        #pragma unroll
        for (int j = 0; j < 8; j++) acc[i][j] = 0.f;

    for (int k0 = 0; k0 < HID; k0 += 16) {
        #pragma unroll
        for (int i = 0; i < 2; i++) {
            int v = tid * 2 + i;           // 0..511 float4s
            int r = v >> 2;                // 0..127
            int kk = (v & 3) * 4;          // 0,4,8,12
            float4 val = make_float4(0.f, 0.f, 0.f, 0.f);
            if (row0 + r < N_NODES)
                val = *(const float4*)(hsrc + (size_t)(row0 + r) * HID + k0 + kk);
            As[kk + 0][r] = val.x; As[kk + 1][r] = val.y;
            As[kk + 2][r] = val.z; As[kk + 3][r] = val.w;
        }
        #pragma unroll
        for (int i = 0; i < 2; i++) {
            int v = tid * 2 + i;           // 0..511
            int kk = v >> 5;               // 0..15
            int c = (v & 31) * 4;          // 0..124
            *(float4*)&Bs[kk][c] = *(const float4*)(W + (size_t)(k0 + kk) * HID + c);
        }
        __syncthreads();
        #pragma unroll
        for (int k = 0; k < 16; k++) {
            float4 a0 = *(const float4*)&As[k][ty * 8];
            float4 a1 = *(const float4*)&As[k][ty * 8 + 4];
            float4 b0 = *(const float4*)&Bs[k][tx * 8];
            float4 b1 = *(const float4*)&Bs[k][tx * 8 + 4];
            float a[8] = {a0.x, a0.y, a0.z, a0.w, a1.x, a1.y, a1.z, a1.w};
            float b[8] = {b0.x, b0.y, b0.z, b0.w, b1.x, b1.y, b1.z, b1.w};
            #pragma unroll
            for (int i = 0; i < 8; i++)
                #pragma unroll
                for (int j = 0; j < 8; j++) acc[i][j] = fmaf(a[i], b[j], acc[i][j]);
        }
        __syncthreads();
    }

    float4 s0 = *(const float4*)(asrc + tx * 8);
    float4 s1 = *(const float4*)(asrc + tx * 8 + 4);
    float4 d0 = *(const float4*)(adst + tx * 8);
    float4 d1 = *(const float4*)(adst + tx * 8 + 4);
    float av[8] = {s0.x, s0.y, s0.z, s0.w, s1.x, s1.y, s1.z, s1.w};
    float dv[8] = {d0.x, d0.y, d0.z, d0.w, d1.x, d1.y, d1.z, d1.w};

    #pragma unroll
    for (int i = 0; i < 8; i++) {
        int r = row0 + ty * 8 + i;
        bool valid = (r < N_NODES);
        if (valid) {
            __half2 h01 = __floats2half2_rn(acc[i][0], acc[i][1]);
            __half2 h23 = __floats2half2_rn(acc[i][2], acc[i][3]);
            __half2 h45 = __floats2half2_rn(acc[i][4], acc[i][5]);
            __half2 h67 = __floats2half2_rn(acc[i][6], acc[i][7]);
            uint4 pk;
            pk.x = *(unsigned*)&h01; pk.y = *(unsigned*)&h23;
            pk.z = *(unsigned*)&h45; pk.w = *(unsigned*)&h67;
            *(uint4*)(d_z16 + (size_t)r * HID + tx * 8) = pk;
        }
        float ps = 0.f, pd = 0.f;
        #pragma unroll
        for (int j = 0; j < 8; j++) {
            ps = fmaf(acc[i][j], av[j], ps);
            pd = fmaf(acc[i][j], dv[j], pd);
        }
        #pragma unroll
        for (int o = 8; o; o >>= 1) {
            ps += __shfl_xor_sync(0xffffffffu, ps, o);
            pd += __shfl_xor_sync(0xffffffffu, pd, o);
        }
        if (valid && tx == 0) { d_zs[r] = ps; d_zd[r] = pd; }
    }
}

// ---------------- chunked lane-parallel softmax aggregation ----------------
// Per 32-edge chunk: lane j loads colsrc/zs and computes exp IN PARALLEL,
// then the inner loop broadcasts (ex, s) via shfl: per edge only
// 2 shfl + 1 uint2 row load + cvt + 4 fma. Single pass (shift-invariant softmax).
__global__ void aggregate_kernel(const float* __restrict__ bvec) {
    int warp = (blockIdx.x * blockDim.x + threadIdx.x) >> 5;
    int lane = threadIdx.x & 31;
    if (warp >= N_NODES) return;
    int beg = d_rowptr[warp], end = d_rowptr[warp + 1];
    float zdn = d_zd[warp];

    float4 acc0 = make_float4(0.f, 0.f, 0.f, 0.f);
    float4 acc1 = make_float4(0.f, 0.f, 0.f, 0.f);
    float den_lane = 0.f;

    for (int c = beg; c < end; c += 32) {
        int idx = c + lane;
        bool v = (idx < end);
        int s_lane = v ? d_colsrc[idx] : 0;               // coalesced
        float ex_lane = 0.f;
        if (v) {
            float e = d_zs[s_lane] + zdn;                  // parallel gather
            e = (e > 0.f) ? e : NEG_SLOPE * e;
            ex_lane = __expf(e);                           // parallel MUFU
        }
        den_lane += ex_lane;
        int nt = end - c; if (nt > 32) nt = 32;

        int t = 0;
        for (; t + 2 <= nt; t += 2) {
            float ex0 = __shfl_sync(0xffffffffu, ex_lane, t);
            int   s0b = __shfl_sync(0xffffffffu, s_lane, t);
            float ex1 = __shfl_sync(0xffffffffu, ex_lane, t + 1);
            int   s1b = __shfl_sync(0xffffffffu, s_lane, t + 1);
            uint2 r0 = ((const uint2*)(d_z16 + (size_t)s0b * HID))[lane];
            uint2 r1 = ((const uint2*)(d_z16 + (size_t)s1b * HID))[lane];
            float2 f00 = __half22float2(*(__half2*)&r0.x);
            float2 f01 = __half22float2(*(__half2*)&r0.y);
            float2 f10 = __half22float2(*(__half2*)&r1.x);
            float2 f11 = __half22float2(*(__half2*)&r1.y);
            acc0.x = fmaf(ex0, f00.x, acc0.x); acc0.y = fmaf(ex0, f00.y, acc0.y);
            acc0.z = fmaf(ex0, f01.x, acc0.z); acc0.w = fmaf(ex0, f01.y, acc0.w);
            acc1.x = fmaf(ex1, f10.x, acc1.x); acc1.y = fmaf(ex1, f10.y, acc1.y);
            acc1.z = fmaf(ex1, f11.x, acc1.z); acc1.w = fmaf(ex1, f11.y, acc1.w);
        }
        if (t < nt) {
            float ex0 = __shfl_sync(0xffffffffu, ex_lane, t);
            int   s0b = __shfl_sync(0xffffffffu, s_lane, t);
            uint2 r0 = ((const uint2*)(d_z16 + (size_t)s0b * HID))[lane];
            float2 f00 = __half22float2(*(__half2*)&r0.x);
            float2 f01 = __half22float2(*(__half2*)&r0.y);
            acc0.x = fmaf(ex0, f00.x, acc0.x); acc0.y = fmaf(ex0, f00.y, acc0.y);
            acc0.z = fmaf(ex0, f01.x, acc0.z); acc0.w = fmaf(ex0, f01.y, acc0.w);
        }
    }

    // denominator: reduce lane-parallel partials across the warp
    float den = den_lane;
    #pragma unroll
    for (int o = 16; o; o >>= 1) den += __shfl_xor_sync(0xffffffffu, den, o);

    float inv = 1.0f / den;
    float4 bb = ((const float4*)bvec)[lane];
    float4 o;
    o.x = fmaxf((acc0.x + acc1.x) * inv + bb.x, 0.f);
    o.y = fmaxf((acc0.y + acc1.y) * inv + bb.y, 0.f);
    o.z = fmaxf((acc0.z + acc1.z) * inv + bb.z, 0.f);
    o.w = fmaxf((acc0.w + acc1.w) * inv + bb.w, 0.f);
    ((float4*)(d_h + (size_t)warp * HID))[lane] = o;
}

// ---------------- action MLP: batched, static smem only ----------------
__global__ __launch_bounds__(128) void action_mlp_kernel(
    const int* __restrict__ asrc, const int* __restrict__ adst,
    const int* __restrict__ atype,
    const float* __restrict__ W1, const float* __restrict__ b1,
    const float* __restrict__ W2, const float* __restrict__ b2,
    float* __restrict__ out) {
    __shared__ __align__(16) float feat[ACT_PER_BLK][260];  // 257 used (pad)
    __shared__ float W1t[16][128];
    __shared__ float red[ACT_PER_BLK][4];
    int tid = threadIdx.x;
    int a0 = blockIdx.x * ACT_PER_BLK;

    #pragma unroll
    for (int a = 0; a < ACT_PER_BLK; a++) {
        int s  = asrc[a0 + a];
        int dd = adst[a0 + a];
        feat[a][tid]       = d_h[(size_t)s  * HID + tid];
        feat[a][128 + tid] = d_h[(size_t)dd * HID + tid];
        if (tid == 0) {
            feat[a][256] = (float)atype[a0 + a];
            feat[a][257] = 0.f; feat[a][258] = 0.f; feat[a][259] = 0.f;
        }
    }
    float acc[ACT_PER_BLK];
    float bj = b1[tid];
    #pragma unroll
    for (int a = 0; a < ACT_PER_BLK; a++) acc[a] = bj;
    __syncthreads();

    for (int k0 = 0; k0 < 256; k0 += 16) {
        #pragma unroll
        for (int i = 0; i < 16; i++) W1t[i][tid] = W1[(size_t)(k0 + i) * HID + tid];
        __syncthreads();
        float w[16];
        #pragma unroll
        for (int i = 0; i < 16; i++) w[i] = W1t[i][tid];
        #pragma unroll
        for (int a = 0; a < ACT_PER_BLK; a++) {
            #pragma unroll
            for (int q = 0; q < 4; q++) {
                float4 f = *(const float4*)&feat[a][k0 + q * 4];
                acc[a] = fmaf(f.x, w[q * 4 + 0], acc[a]);
                acc[a] = fmaf(f.y, w[q * 4 + 1], acc[a]);
                acc[a] = fmaf(f.z, w[q * 4 + 2], acc[a]);
                acc[a] = fmaf(f.w, w[q * 4 + 3], acc[a]);
            }
        }
        __syncthreads();
    }
    {
        float w = W1[(size_t)256 * HID + tid];
        #pragma unroll
        for (int a = 0; a < ACT_PER_BLK; a++) acc[a] = fmaf(feat[a][256], w, acc[a]);
    }

    float w2j = W2[tid];
    float b2v = b2[0];
    int lane = tid & 31, wp = tid >> 5;
    #pragma unroll
    for (int a = 0; a < ACT_PER_BLK; a++) {
        float c = fmaxf(acc[a], 0.f) * w2j;
        #pragma unroll
        for (int o = 16; o; o >>= 1) c += __shfl_xor_sync(0xffffffffu, c, o);
        if (lane == 0) red[a][wp] = c;
    }
    __syncthreads();
    if (tid < ACT_PER_BLK)
        out[a0 + tid] = red[tid][0] + red[tid][1] + red[tid][2] + red[tid][3] + b2v;
}

// ---------------- launch ----------------
extern "C" void kernel_launch(void* const* d_in, const int* in_sizes, int n_in,
                              void* d_out, int out_size) {
    const float* x     = (const float*)d_in[0];
    const int*   ei    = (const int*)d_in[1];     // int32 (JAX x64 disabled)
    const int*   a_src = (const int*)d_in[2];     // int32
    const int*   a_dst = (const int*)d_in[3];     // int32
    const int*   a_ty  = (const int*)d_in[4];
    const float* gW    = (const float*)d_in[5];
    const float* ga_s  = (const float*)d_in[6];
    const float* ga_d  = (const float*)d_in[7];
    const float* gb    = (const float*)d_in[8];
    const float* W1    = (const float*)d_in[9];
    const float* b1    = (const float*)d_in[10];
    const float* W2    = (const float*)d_in[11];
    const float* b2    = (const float*)d_in[12];
    float* out = (float*)d_out;

    // CSR build (by dst)
    zero_deg_kernel<<<(N_NODES + 255) / 256, 256>>>();
    count_deg_kernel<<<(E_TOT + 255) / 256, 256>>>(ei);
    scan_deg_kernel<<<1, 1024>>>();
    scatter_edges_kernel<<<(E_TOT + 255) / 256, 256>>>(ei);

    // 3 GAT layers (dots fused into GEMM epilogue; z stored fp16)
    for (int l = 0; l < N_LAYERS; l++) {
        gemm_zw_kernel<<<(N_NODES + 127) / 128, 256>>>(x, gW + (size_t)l * HID * HID,
                                                       ga_s + l * HID, ga_d + l * HID, l);
        aggregate_kernel<<<(N_NODES * 32 + 255) / 256, 256>>>(gb + l * HID);
    }

    // action scoring MLP
    action_mlp_kernel<<<N_ACT / ACT_PER_BLK, 128>>>(a_src, a_dst, a_ty, W1, b1, W2, b2, out);
}